// round 15
// baseline (speedup 1.0000x reference)
#include <cuda_runtime.h>
#include <stdint.h>

#define N_NODES 100000
#define N_EDGES 1600000
#define LOG2E 1.4426950408889634f
#define SCAN_B 1024
#define SCAN_NB ((N_NODES + SCAN_B - 1) / SCAN_B)  // 98

// ---------------- device scratch (no allocations allowed) ----------------
__device__ int    g_deg[N_NODES];                 // zero-initialized; re-zeroed by k_scan each run
__device__ unsigned long long g_desc[SCAN_NB];    // lookback descriptors; re-zeroed by k_scatter
__device__ int    g_rowptr[N_NODES + 1];
__device__ int    g_pos[N_NODES];
__device__ int    g_srcs[N_EDGES];
__device__ float4 g_h2[N_NODES];
__device__ float  g_a2s[N_NODES];
__device__ float  g_a2d[N_NODES];
__device__ float  g_ps[8], g_qs[8], g_pd[8], g_qd[8];

__device__ __forceinline__ float ex2f(float x) {
    float r;
    asm("ex2.approx.ftz.f32 %0, %1;" : "=f"(r) : "f"(x));
    return r;
}

// Per-warp int64-vs-int32 detection: for int64 edge data (values < 2^31),
// the odd 32-bit words of the first 64 elements are all zero; for int32 they
// are random node ids (all-zero has ~0 probability).
__device__ __forceinline__ int detect_is64(const int* __restrict__ ei) {
    int lane = threadIdx.x & 31;
    int nz = ei[2 * lane + 1] | ei[2 * (lane + 32) + 1];
#pragma unroll
    for (int off = 16; off > 0; off >>= 1) nz |= __shfl_xor_sync(0xffffffffu, nz, off);
    return nz == 0;
}

// ---------------- hist: 4 edges/thread, vector loads ----------------
__global__ void __launch_bounds__(256) k_hist(const int* __restrict__ ei) {
    int is64 = detect_is64(ei);
    int e0 = (blockIdx.x * blockDim.x + threadIdx.x) * 4;
    if (e0 >= N_EDGES) return;
    int d0, d1, d2, d3;
    if (is64) {
        const longlong2* p = (const longlong2*)((const long long*)ei + N_EDGES + e0);
        longlong2 a = __ldg(&p[0]);
        longlong2 b = __ldg(&p[1]);
        d0 = (int)a.x; d1 = (int)a.y; d2 = (int)b.x; d3 = (int)b.y;
    } else {
        int4 a = __ldg((const int4*)(ei + N_EDGES + e0));
        d0 = a.x; d1 = a.y; d2 = a.z; d3 = a.w;
    }
    if ((unsigned)d0 < (unsigned)N_NODES) atomicAdd(&g_deg[d0], 1);
    if ((unsigned)d1 < (unsigned)N_NODES) atomicAdd(&g_deg[d1], 1);
    if ((unsigned)d2 < (unsigned)N_NODES) atomicAdd(&g_deg[d2], 1);
    if ((unsigned)d3 < (unsigned)N_NODES) atomicAdd(&g_deg[d3], 1);
}

// ---------------- single-pass decoupled-lookback scan ----------------
// Also: re-zeroes g_deg for the next graph replay, writes rowptr+pos, and
// block 0 computes the rank-2 attention projections (g_ps/qs/pd/qd).
__global__ void __launch_bounds__(SCAN_B) k_scan(const float* __restrict__ W1,
                                                 const float* __restrict__ as1,
                                                 const float* __restrict__ ad1) {
    __shared__ int wsum[32];
    __shared__ int s_base;
    int t = threadIdx.x;
    int b = blockIdx.x;
    int lane = t & 31;
    int wid = t >> 5;
    int i = b * SCAN_B + t;

    int v = 0;
    if (i < N_NODES) {
        v = g_deg[i];
        g_deg[i] = 0;  // restore invariant for next replay
    }
    // warp inclusive scan
    int wi = v;
#pragma unroll
    for (int off = 1; off < 32; off <<= 1) {
        int u = __shfl_up_sync(0xffffffffu, wi, off);
        if (lane >= off) wi += u;
    }
    if (lane == 31) wsum[wid] = wi;
    __syncthreads();
    if (wid == 0) {
        int w = wsum[lane];
#pragma unroll
        for (int off = 1; off < 32; off <<= 1) {
            int u = __shfl_up_sync(0xffffffffu, w, off);
            if (lane >= off) w += u;
        }
        wsum[lane] = w;
    }
    __syncthreads();
    int incl = wi + (wid ? wsum[wid - 1] : 0);
    int blockTotal = wsum[31];

    // decoupled lookback (t==0); 98 blocks <= 148 SMs -> all resident, no deadlock
    if (t == 0) {
        if (b == 0) {
            atomicExch(&g_desc[0], (2ull << 32) | (unsigned)blockTotal);
            s_base = 0;
        } else {
            atomicExch(&g_desc[b], (1ull << 32) | (unsigned)blockTotal);
            long long sum = 0;
            int j = b - 1;
            for (;;) {
                unsigned long long d;
                do {
                    d = *(volatile unsigned long long*)&g_desc[j];
                } while ((d >> 32) == 0ull);
                sum += (int)(unsigned)(d & 0xffffffffull);
                if ((d >> 32) == 2ull) break;
                j--;
            }
            s_base = (int)sum;
            atomicExch(&g_desc[b], (2ull << 32) | (unsigned)(sum + blockTotal));
        }
    }
    __syncthreads();
    int base = s_base;
    if (i < N_NODES) {
        int exc = base + incl - v;
        g_rowptr[i] = exc;
        g_pos[i] = exc;
        if (i == N_NODES - 1) g_rowptr[N_NODES] = base + incl;
    }

    // rank-2 projection precompute (block 0, 8 threads)
    if (b == 0 && t < 8) {
        int h = t;
        float ps = 0.f, qs = 0.f, pd = 0.f, qd = 0.f;
        for (int c = 0; c < 16; c++) {
            int idx = h * 16 + c;
            float w0 = W1[idx], w1 = W1[128 + idx];
            float a = as1[idx], d = ad1[idx];
            ps += w0 * a;
            qs += w1 * a;
            pd += w0 * d;
            qd += w1 * d;
        }
        g_ps[h] = ps * LOG2E;
        g_qs[h] = qs * LOG2E;
        g_pd[h] = pd * LOG2E;
        g_qd[h] = qd * LOG2E;
    }
}

// ---------------- scatter: 4 edges/thread; also re-zero g_desc ----------------
__global__ void __launch_bounds__(256) k_scatter(const int* __restrict__ ei) {
    int is64 = detect_is64(ei);
    int gtid = blockIdx.x * blockDim.x + threadIdx.x;
    if (gtid < SCAN_NB) g_desc[gtid] = 0ull;  // restore for next replay
    int e0 = gtid * 4;
    if (e0 >= N_EDGES) return;
    int s0, s1, s2, s3, d0, d1, d2, d3;
    if (is64) {
        const longlong2* ps = (const longlong2*)((const long long*)ei + e0);
        const longlong2* pd = (const longlong2*)((const long long*)ei + N_EDGES + e0);
        longlong2 a = __ldg(&ps[0]), b = __ldg(&ps[1]);
        longlong2 c = __ldg(&pd[0]), d = __ldg(&pd[1]);
        s0 = (int)a.x; s1 = (int)a.y; s2 = (int)b.x; s3 = (int)b.y;
        d0 = (int)c.x; d1 = (int)c.y; d2 = (int)d.x; d3 = (int)d.y;
    } else {
        int4 a = __ldg((const int4*)(ei + e0));
        int4 c = __ldg((const int4*)(ei + N_EDGES + e0));
        s0 = a.x; s1 = a.y; s2 = a.z; s3 = a.w;
        d0 = c.x; d1 = c.y; d2 = c.z; d3 = c.w;
    }
#define SCAT(ss, dd)                                                            \
    if ((unsigned)(dd) < (unsigned)N_NODES && (unsigned)(ss) < (unsigned)N_NODES) { \
        int p = atomicAdd(&g_pos[dd], 1);                                       \
        if ((unsigned)p < (unsigned)N_EDGES) g_srcs[p] = (ss);                  \
    }
    SCAT(s0, d0)
    SCAT(s1, d1)
    SCAT(s2, d2)
    SCAT(s3, d3)
#undef SCAT
}

// ---------------- layer 1: edge softmax-aggregate + node transform + W2 fold ----------------
// warp per dst node; lane = 8*edge_stripe + head (4 stripes x 8 heads)
__global__ void __launch_bounds__(256) k_layer1(
    const float* __restrict__ x,
    const float* __restrict__ W1,
    const float* __restrict__ b1,
    const float* __restrict__ W2,
    const float* __restrict__ as2,
    const float* __restrict__ ad2) {
    int warp = (blockIdx.x * blockDim.x + threadIdx.x) >> 5;
    if (warp >= N_NODES) return;
    int lane = threadIdx.x & 31;
    int h = lane & 7;
    int es = lane >> 3;

    const float2* x2 = (const float2*)x;
    float2 xn = __ldg(&x2[warp]);
    float P = g_ps[h], Q = g_qs[h];
    float A = fmaf(xn.x, g_pd[h], xn.y * g_qd[h]);  // log2e * a_dst[n,h]

    int beg = g_rowptr[warp];
    int end = g_rowptr[warp + 1];

    float S0 = 0.f, S1 = 0.f, SS = 0.f;
    int i = beg + es;
    int s = (i < end) ? __ldg(&g_srcs[i]) : 0;
    float2 xv = __ldg(&x2[s]);
    while (i < end) {
        int i2 = i + 4;
        int s2 = (i2 < end) ? __ldg(&g_srcs[i2]) : 0;
        float2 xv2 = __ldg(&x2[s2]);                  // pipelined gather
        float t = fmaf(xv.y, Q, fmaf(xv.x, P, A));    // log2e*(a_src+a_dst)
        t = fmaxf(t, 0.2f * t);                       // leaky relu (scale-invariant)
        float ex = ex2f(t);                           // exp(lrelu(e))
        S0 = fmaf(ex, xv.x, S0);
        S1 = fmaf(ex, xv.y, S1);
        SS += ex;
        i = i2;
        xv = xv2;
    }
    // reduce over the 4 edge stripes (lanes differing by 8, 16)
    S0 += __shfl_xor_sync(0xffffffffu, S0, 8);
    S0 += __shfl_xor_sync(0xffffffffu, S0, 16);
    S1 += __shfl_xor_sync(0xffffffffu, S1, 8);
    S1 += __shfl_xor_sync(0xffffffffu, S1, 16);
    SS += __shfl_xor_sync(0xffffffffu, SS, 8);
    SS += __shfl_xor_sync(0xffffffffu, SS, 16);

    // redistribute: lane l now produces channels 4l..4l+3, head = l>>2
    int hl = lane >> 2;
    float s0 = __shfl_sync(0xffffffffu, S0, hl);
    float s1 = __shfl_sync(0xffffffffu, S1, hl);
    float ss = __shfl_sync(0xffffffffu, SS, hl);
    float inv = 1.0f / (ss + 1e-16f);

    // out1[c] = (S0*W1[0,c] + S1*W1[1,c])/sum + b1[c], relu; fold into W2
    float hp0 = 0.f, hp1 = 0.f, hp2 = 0.f, hp3 = 0.f;
#pragma unroll
    for (int k = 0; k < 4; k++) {
        int c = 4 * lane + k;
        float o = fmaf(s0, __ldg(&W1[c]), s1 * __ldg(&W1[128 + c])) * inv + __ldg(&b1[c]);
        o = fmaxf(o, 0.0f);  // relu
        hp0 = fmaf(o, __ldg(&W2[c * 4 + 0]), hp0);
        hp1 = fmaf(o, __ldg(&W2[c * 4 + 1]), hp1);
        hp2 = fmaf(o, __ldg(&W2[c * 4 + 2]), hp2);
        hp3 = fmaf(o, __ldg(&W2[c * 4 + 3]), hp3);
    }
#pragma unroll
    for (int off = 16; off > 0; off >>= 1) {
        hp0 += __shfl_xor_sync(0xffffffffu, hp0, off);
        hp1 += __shfl_xor_sync(0xffffffffu, hp1, off);
        hp2 += __shfl_xor_sync(0xffffffffu, hp2, off);
        hp3 += __shfl_xor_sync(0xffffffffu, hp3, off);
    }
    if (lane == 0) {
        g_h2[warp] = make_float4(hp0, hp1, hp2, hp3);
        float a0 = __ldg(&as2[0]), a1 = __ldg(&as2[1]), a2 = __ldg(&as2[2]), a3 = __ldg(&as2[3]);
        float d0 = __ldg(&ad2[0]), d1 = __ldg(&ad2[1]), d2 = __ldg(&ad2[2]), d3 = __ldg(&ad2[3]);
        g_a2s[warp] = (hp0 * a0 + hp1 * a1 + hp2 * a2 + hp3 * a3) * LOG2E;
        g_a2d[warp] = (hp0 * d0 + hp1 * d1 + hp2 * d2 + hp3 * d3) * LOG2E;
    }
}

// ---------------- layer 2: edge softmax-aggregate + bias + log_softmax ----------------
__global__ void __launch_bounds__(256) k_layer2(const float* __restrict__ b2,
                                                float* __restrict__ out) {
    int warp = (blockIdx.x * blockDim.x + threadIdx.x) >> 5;
    if (warp >= N_NODES) return;
    int lane = threadIdx.x & 31;

    float a2dn = g_a2d[warp];
    int beg = g_rowptr[warp];
    int end = g_rowptr[warp + 1];

    float a0 = 0.f, a1 = 0.f, a2 = 0.f, a3 = 0.f, ss = 0.f;
    int i = beg + lane;
    int s = (i < end) ? __ldg(&g_srcs[i]) : 0;
    float av = g_a2s[s];
    float4 hv = g_h2[s];
    while (i < end) {
        int i2 = i + 32;
        int s2 = (i2 < end) ? __ldg(&g_srcs[i2]) : 0;
        float av2 = g_a2s[s2];
        float4 hv2 = g_h2[s2];
        float t = av + a2dn;
        t = fmaxf(t, 0.2f * t);
        float ex = ex2f(t);
        a0 = fmaf(ex, hv.x, a0);
        a1 = fmaf(ex, hv.y, a1);
        a2 = fmaf(ex, hv.z, a2);
        a3 = fmaf(ex, hv.w, a3);
        ss += ex;
        i = i2;
        av = av2;
        hv = hv2;
    }
#pragma unroll
    for (int off = 16; off > 0; off >>= 1) {
        a0 += __shfl_xor_sync(0xffffffffu, a0, off);
        a1 += __shfl_xor_sync(0xffffffffu, a1, off);
        a2 += __shfl_xor_sync(0xffffffffu, a2, off);
        a3 += __shfl_xor_sync(0xffffffffu, a3, off);
        ss += __shfl_xor_sync(0xffffffffu, ss, off);
    }
    if (lane == 0) {
        float inv = 1.0f / (ss + 1e-16f);
        float o0 = a0 * inv + __ldg(&b2[0]);
        float o1 = a1 * inv + __ldg(&b2[1]);
        float o2 = a2 * inv + __ldg(&b2[2]);
        float o3 = a3 * inv + __ldg(&b2[3]);
        float m = fmaxf(fmaxf(o0, o1), fmaxf(o2, o3));
        float se = expf(o0 - m) + expf(o1 - m) + expf(o2 - m) + expf(o3 - m);
        float ls = m + logf(se);
        ((float4*)out)[warp] = make_float4(o0 - ls, o1 - ls, o2 - ls, o3 - ls);
    }
}

// ---------------- launch ----------------
extern "C" void kernel_launch(void* const* d_in, const int* in_sizes, int n_in,
                              void* d_out, int out_size) {
    const float* x   = (const float*)d_in[0];
    const int*   ei  = (const int*)d_in[1];  // raw 32-bit view; dtype detected per-warp
    const float* W1  = (const float*)d_in[2];
    const float* as1 = (const float*)d_in[3];
    const float* ad1 = (const float*)d_in[4];
    const float* b1  = (const float*)d_in[5];
    const float* W2  = (const float*)d_in[6];
    const float* as2 = (const float*)d_in[7];
    const float* ad2 = (const float*)d_in[8];
    const float* b2  = (const float*)d_in[9];
    float*       out = (float*)d_out;

    int eb = (N_EDGES / 4 + 255) / 256;
    k_hist<<<eb, 256>>>(ei);
    k_scan<<<SCAN_NB, SCAN_B>>>(W1, as1, ad1);
    k_scatter<<<eb, 256>>>(ei);
    k_layer1<<<(N_NODES * 32 + 255) / 256, 256>>>(x, W1, b1, W2, as2, ad2);
    k_layer2<<<(N_NODES * 32 + 255) / 256, 256>>>(b2, out);
}

// round 16
// speedup vs baseline: 1.3656x; 1.3656x over previous
#include <cuda_runtime.h>
#include <stdint.h>

#define N_NODES 100000
#define N_EDGES 1600000
#define LOG2E 1.4426950408889634f
#define SCAN_B 1024
#define SCAN_NB ((N_NODES + SCAN_B - 1) / SCAN_B)  // 98

// ---------------- device scratch (no allocations allowed) ----------------
__device__ int    g_deg[N_NODES];               // zero-init; re-zeroed by k_scan each run
__device__ unsigned long long g_desc[SCAN_NB];  // lookback descriptors; re-zeroed by k_scatter
__device__ int    g_rowptr[N_NODES + 1];
__device__ int    g_pos[N_NODES];
__device__ int    g_srcs[N_EDGES];
__device__ float2 g_ex[N_EDGES];                // staged x[src] per CSR edge slot
__device__ float  g_e2a[N_EDGES];               // staged a2s[src] per CSR edge slot
__device__ float4 g_e2h[N_EDGES];               // staged h2[src] per CSR edge slot
__device__ float4 g_h2[N_NODES];
__device__ float  g_a2s[N_NODES];
__device__ float  g_a2d[N_NODES];
__device__ float4 g_pq[8];                      // (ps,qs,pd,qd)*log2e per head

__device__ __forceinline__ float ex2f(float x) {
    float r;
    asm("ex2.approx.ftz.f32 %0, %1;" : "=f"(r) : "f"(x));
    return r;
}

// Per-warp int64-vs-int32 detection: for int64 edge data (values < 2^31),
// odd 32-bit words of the first 64 elements are all zero.
__device__ __forceinline__ int detect_is64(const int* __restrict__ ei) {
    int lane = threadIdx.x & 31;
    int nz = ei[2 * lane + 1] | ei[2 * (lane + 32) + 1];
#pragma unroll
    for (int off = 16; off > 0; off >>= 1) nz |= __shfl_xor_sync(0xffffffffu, nz, off);
    return nz == 0;
}

// ---------------- hist: 4 edges/thread, vector loads ----------------
__global__ void __launch_bounds__(256) k_hist(const int* __restrict__ ei) {
    int is64 = detect_is64(ei);
    int e0 = (blockIdx.x * blockDim.x + threadIdx.x) * 4;
    if (e0 >= N_EDGES) return;
    int d0, d1, d2, d3;
    if (is64) {
        const longlong2* p = (const longlong2*)((const long long*)ei + N_EDGES + e0);
        longlong2 a = __ldg(&p[0]);
        longlong2 b = __ldg(&p[1]);
        d0 = (int)a.x; d1 = (int)a.y; d2 = (int)b.x; d3 = (int)b.y;
    } else {
        int4 a = __ldg((const int4*)(ei + N_EDGES + e0));
        d0 = a.x; d1 = a.y; d2 = a.z; d3 = a.w;
    }
    if ((unsigned)d0 < (unsigned)N_NODES) atomicAdd(&g_deg[d0], 1);
    if ((unsigned)d1 < (unsigned)N_NODES) atomicAdd(&g_deg[d1], 1);
    if ((unsigned)d2 < (unsigned)N_NODES) atomicAdd(&g_deg[d2], 1);
    if ((unsigned)d3 < (unsigned)N_NODES) atomicAdd(&g_deg[d3], 1);
}

// ---------------- single-pass decoupled-lookback scan ----------------
__global__ void __launch_bounds__(SCAN_B) k_scan(const float* __restrict__ W1,
                                                 const float* __restrict__ as1,
                                                 const float* __restrict__ ad1) {
    __shared__ int wsum[32];
    __shared__ int s_base;
    int t = threadIdx.x;
    int b = blockIdx.x;
    int lane = t & 31;
    int wid = t >> 5;
    int i = b * SCAN_B + t;

    int v = 0;
    if (i < N_NODES) {
        v = g_deg[i];
        g_deg[i] = 0;  // restore invariant for next replay
    }
    int wi = v;
#pragma unroll
    for (int off = 1; off < 32; off <<= 1) {
        int u = __shfl_up_sync(0xffffffffu, wi, off);
        if (lane >= off) wi += u;
    }
    if (lane == 31) wsum[wid] = wi;
    __syncthreads();
    if (wid == 0) {
        int w = wsum[lane];
#pragma unroll
        for (int off = 1; off < 32; off <<= 1) {
            int u = __shfl_up_sync(0xffffffffu, w, off);
            if (lane >= off) w += u;
        }
        wsum[lane] = w;
    }
    __syncthreads();
    int incl = wi + (wid ? wsum[wid - 1] : 0);
    int blockTotal = wsum[31];

    if (t == 0) {
        if (b == 0) {
            atomicExch(&g_desc[0], (2ull << 32) | (unsigned)blockTotal);
            s_base = 0;
        } else {
            atomicExch(&g_desc[b], (1ull << 32) | (unsigned)blockTotal);
            long long sum = 0;
            int j = b - 1;
            for (;;) {
                unsigned long long d;
                do {
                    d = *(volatile unsigned long long*)&g_desc[j];
                } while ((d >> 32) == 0ull);
                sum += (int)(unsigned)(d & 0xffffffffull);
                if ((d >> 32) == 2ull) break;
                j--;
            }
            s_base = (int)sum;
            atomicExch(&g_desc[b], (2ull << 32) | (unsigned)(sum + blockTotal));
        }
    }
    __syncthreads();
    int base = s_base;
    if (i < N_NODES) {
        int exc = base + incl - v;
        g_rowptr[i] = exc;
        g_pos[i] = exc;
        if (i == N_NODES - 1) g_rowptr[N_NODES] = base + incl;
    }

    // rank-2 projection precompute (block 0, 8 threads)
    if (b == 0 && t < 8) {
        int h = t;
        float ps = 0.f, qs = 0.f, pd = 0.f, qd = 0.f;
        for (int c = 0; c < 16; c++) {
            int idx = h * 16 + c;
            float w0 = W1[idx], w1 = W1[128 + idx];
            float a = as1[idx], d = ad1[idx];
            ps += w0 * a;
            qs += w1 * a;
            pd += w0 * d;
            qd += w1 * d;
        }
        g_pq[h] = make_float4(ps * LOG2E, qs * LOG2E, pd * LOG2E, qd * LOG2E);
    }
}

// ---------------- scatter: 4 edges/thread; also stage x[src] per edge slot ----------------
__global__ void __launch_bounds__(256) k_scatter(const int* __restrict__ ei,
                                                 const float* __restrict__ x) {
    int is64 = detect_is64(ei);
    int gtid = blockIdx.x * blockDim.x + threadIdx.x;
    if (gtid < SCAN_NB) g_desc[gtid] = 0ull;  // restore for next replay
    int e0 = gtid * 4;
    if (e0 >= N_EDGES) return;
    const float2* x2 = (const float2*)x;
    int s0, s1, s2, s3, d0, d1, d2, d3;
    if (is64) {
        const longlong2* ps = (const longlong2*)((const long long*)ei + e0);
        const longlong2* pd = (const longlong2*)((const long long*)ei + N_EDGES + e0);
        longlong2 a = __ldg(&ps[0]), b = __ldg(&ps[1]);
        longlong2 c = __ldg(&pd[0]), d = __ldg(&pd[1]);
        s0 = (int)a.x; s1 = (int)a.y; s2 = (int)b.x; s3 = (int)b.y;
        d0 = (int)c.x; d1 = (int)c.y; d2 = (int)d.x; d3 = (int)d.y;
    } else {
        int4 a = __ldg((const int4*)(ei + e0));
        int4 c = __ldg((const int4*)(ei + N_EDGES + e0));
        s0 = a.x; s1 = a.y; s2 = a.z; s3 = a.w;
        d0 = c.x; d1 = c.y; d2 = c.z; d3 = c.w;
    }
#define SCAT(ss, dd)                                                            \
    if ((unsigned)(dd) < (unsigned)N_NODES && (unsigned)(ss) < (unsigned)N_NODES) { \
        int p = atomicAdd(&g_pos[dd], 1);                                       \
        if ((unsigned)p < (unsigned)N_EDGES) {                                  \
            g_srcs[p] = (ss);                                                   \
            g_ex[p] = __ldg(&x2[ss]);                                           \
        }                                                                       \
    }
    SCAT(s0, d0)
    SCAT(s1, d1)
    SCAT(s2, d2)
    SCAT(s3, d3)
#undef SCAT
}

// ---------------- layer 1: coalesced edge stream + node transform + W2 fold ----------------
// warp per dst node; lane = 8*edge_stripe + head (4 stripes x 8 heads)
__global__ void __launch_bounds__(256) k_layer1(
    const float* __restrict__ x,
    const float* __restrict__ W1,
    const float* __restrict__ b1,
    const float* __restrict__ W2,
    const float* __restrict__ as2,
    const float* __restrict__ ad2) {
    int warp = (blockIdx.x * blockDim.x + threadIdx.x) >> 5;
    if (warp >= N_NODES) return;
    int lane = threadIdx.x & 31;
    int h = lane & 7;
    int es = lane >> 3;

    float4 pq = g_pq[h];
    const float2* x2 = (const float2*)x;
    float2 xn = __ldg(&x2[warp]);
    float P = pq.x, Q = pq.y;
    float A = fmaf(xn.x, pq.z, xn.y * pq.w);  // log2e * a_dst[n,h]

    int beg = g_rowptr[warp];
    int end = g_rowptr[warp + 1];

    float S0 = 0.f, S1 = 0.f, SS = 0.f;
    for (int i = beg + es; i < end; i += 4) {
        float2 xs = g_ex[i];                        // coalesced/broadcast stream
        float t = fmaf(xs.y, Q, fmaf(xs.x, P, A));  // log2e*(a_src+a_dst)
        t = fmaxf(t, 0.2f * t);                     // leaky relu
        float ex = ex2f(t);                         // exp(lrelu(e))
        S0 = fmaf(ex, xs.x, S0);
        S1 = fmaf(ex, xs.y, S1);
        SS += ex;
    }
    // reduce over the 4 edge stripes
    S0 += __shfl_xor_sync(0xffffffffu, S0, 8);
    S0 += __shfl_xor_sync(0xffffffffu, S0, 16);
    S1 += __shfl_xor_sync(0xffffffffu, S1, 8);
    S1 += __shfl_xor_sync(0xffffffffu, S1, 16);
    SS += __shfl_xor_sync(0xffffffffu, SS, 8);
    SS += __shfl_xor_sync(0xffffffffu, SS, 16);

    // redistribute: lane l produces channels 4l..4l+3, head = l>>2
    int hl = lane >> 2;
    float s0 = __shfl_sync(0xffffffffu, S0, hl);
    float s1 = __shfl_sync(0xffffffffu, S1, hl);
    float ss = __shfl_sync(0xffffffffu, SS, hl);
    float inv = 1.0f / (ss + 1e-16f);

    // out1[c] = (S0*W1[0,c] + S1*W1[1,c])/sum + b1[c], relu; fold into W2
    float4 w1a = __ldg((const float4*)(W1 + 4 * lane));
    float4 w1b = __ldg((const float4*)(W1 + 128 + 4 * lane));
    float4 bb = __ldg((const float4*)(b1 + 4 * lane));
    float o0 = fmaxf(fmaf(s0, w1a.x, s1 * w1b.x) * inv + bb.x, 0.f);
    float o1 = fmaxf(fmaf(s0, w1a.y, s1 * w1b.y) * inv + bb.y, 0.f);
    float o2 = fmaxf(fmaf(s0, w1a.z, s1 * w1b.z) * inv + bb.z, 0.f);
    float o3 = fmaxf(fmaf(s0, w1a.w, s1 * w1b.w) * inv + bb.w, 0.f);
    float4 w20 = __ldg((const float4*)(W2 + (4 * lane + 0) * 4));
    float4 w21 = __ldg((const float4*)(W2 + (4 * lane + 1) * 4));
    float4 w22 = __ldg((const float4*)(W2 + (4 * lane + 2) * 4));
    float4 w23 = __ldg((const float4*)(W2 + (4 * lane + 3) * 4));
    float hp0 = o0 * w20.x + o1 * w21.x + o2 * w22.x + o3 * w23.x;
    float hp1 = o0 * w20.y + o1 * w21.y + o2 * w22.y + o3 * w23.y;
    float hp2 = o0 * w20.z + o1 * w21.z + o2 * w22.z + o3 * w23.z;
    float hp3 = o0 * w20.w + o1 * w21.w + o2 * w22.w + o3 * w23.w;
#pragma unroll
    for (int off = 16; off > 0; off >>= 1) {
        hp0 += __shfl_xor_sync(0xffffffffu, hp0, off);
        hp1 += __shfl_xor_sync(0xffffffffu, hp1, off);
        hp2 += __shfl_xor_sync(0xffffffffu, hp2, off);
        hp3 += __shfl_xor_sync(0xffffffffu, hp3, off);
    }
    if (lane == 0) {
        g_h2[warp] = make_float4(hp0, hp1, hp2, hp3);
        float4 a = __ldg((const float4*)as2);
        float4 d = __ldg((const float4*)ad2);
        g_a2s[warp] = (hp0 * a.x + hp1 * a.y + hp2 * a.z + hp3 * a.w) * LOG2E;
        g_a2d[warp] = (hp0 * d.x + hp1 * d.y + hp2 * d.z + hp3 * d.w) * LOG2E;
    }
}

// ---------------- stage2: gather (a2s, h2) of each edge's src into CSR order ----------------
__global__ void __launch_bounds__(256) k_stage2() {
    int e0 = (blockIdx.x * blockDim.x + threadIdx.x) * 4;
    if (e0 >= N_EDGES) return;
    int4 s4 = *(const int4*)(g_srcs + e0);
    float a0 = g_a2s[s4.x];
    float a1 = g_a2s[s4.y];
    float a2 = g_a2s[s4.z];
    float a3 = g_a2s[s4.w];
    float4 h0 = g_h2[s4.x];
    float4 h1 = g_h2[s4.y];
    float4 h2v = g_h2[s4.z];
    float4 h3 = g_h2[s4.w];
    *(float4*)(g_e2a + e0) = make_float4(a0, a1, a2, a3);
    g_e2h[e0 + 0] = h0;
    g_e2h[e0 + 1] = h1;
    g_e2h[e0 + 2] = h2v;
    g_e2h[e0 + 3] = h3;
}

// ---------------- layer 2: coalesced edge stream + bias + log_softmax ----------------
__global__ void __launch_bounds__(256) k_layer2(const float* __restrict__ b2,
                                                float* __restrict__ out) {
    int warp = (blockIdx.x * blockDim.x + threadIdx.x) >> 5;
    if (warp >= N_NODES) return;
    int lane = threadIdx.x & 31;

    float a2dn = g_a2d[warp];
    int beg = g_rowptr[warp];
    int end = g_rowptr[warp + 1];

    float a0 = 0.f, a1 = 0.f, a2 = 0.f, a3 = 0.f, ss = 0.f;
    for (int i = beg + lane; i < end; i += 32) {
        float t = g_e2a[i] + a2dn;
        t = fmaxf(t, 0.2f * t);
        float ex = ex2f(t);
        float4 hv = g_e2h[i];
        a0 = fmaf(ex, hv.x, a0);
        a1 = fmaf(ex, hv.y, a1);
        a2 = fmaf(ex, hv.z, a2);
        a3 = fmaf(ex, hv.w, a3);
        ss += ex;
    }
#pragma unroll
    for (int off = 16; off > 0; off >>= 1) {
        a0 += __shfl_xor_sync(0xffffffffu, a0, off);
        a1 += __shfl_xor_sync(0xffffffffu, a1, off);
        a2 += __shfl_xor_sync(0xffffffffu, a2, off);
        a3 += __shfl_xor_sync(0xffffffffu, a3, off);
        ss += __shfl_xor_sync(0xffffffffu, ss, off);
    }
    if (lane == 0) {
        float inv = 1.0f / (ss + 1e-16f);
        float4 bv = __ldg((const float4*)b2);
        float o0 = a0 * inv + bv.x;
        float o1 = a1 * inv + bv.y;
        float o2 = a2 * inv + bv.z;
        float o3 = a3 * inv + bv.w;
        float m = fmaxf(fmaxf(o0, o1), fmaxf(o2, o3));
        float se = expf(o0 - m) + expf(o1 - m) + expf(o2 - m) + expf(o3 - m);
        float ls = m + logf(se);
        ((float4*)out)[warp] = make_float4(o0 - ls, o1 - ls, o2 - ls, o3 - ls);
    }
}

// ---------------- launch ----------------
extern "C" void kernel_launch(void* const* d_in, const int* in_sizes, int n_in,
                              void* d_out, int out_size) {
    const float* x   = (const float*)d_in[0];
    const int*   ei  = (const int*)d_in[1];  // raw 32-bit view; dtype detected per-warp
    const float* W1  = (const float*)d_in[2];
    const float* as1 = (const float*)d_in[3];
    const float* ad1 = (const float*)d_in[4];
    const float* b1  = (const float*)d_in[5];
    const float* W2  = (const float*)d_in[6];
    const float* as2 = (const float*)d_in[7];
    const float* ad2 = (const float*)d_in[8];
    const float* b2  = (const float*)d_in[9];
    float*       out = (float*)d_out;

    int eb = (N_EDGES / 4 + 255) / 256;
    k_hist<<<eb, 256>>>(ei);
    k_scan<<<SCAN_NB, SCAN_B>>>(W1, as1, ad1);
    k_scatter<<<eb, 256>>>(ei, x);
    k_layer1<<<(N_NODES * 32 + 255) / 256, 256>>>(x, W1, b1, W2, as2, ad2);
    k_stage2<<<eb, 256>>>();
    k_layer2<<<(N_NODES * 32 + 255) / 256, 256>>>(b2, out);
}

// round 17
// speedup vs baseline: 1.3662x; 1.0004x over previous
#include <cuda_runtime.h>
#include <stdint.h>

#define N_NODES 100000
#define N_EDGES 1600000
#define LOG2E 1.4426950408889634f
#define SCAN_B 1024
#define SCAN_NB ((N_NODES + SCAN_B - 1) / SCAN_B)  // 98

// ---------------- device scratch (no allocations allowed) ----------------
__device__ int    g_deg[N_NODES];               // zero-init; re-zeroed by k_scan each run
__device__ unsigned long long g_desc[SCAN_NB];  // lookback descriptors; re-zeroed by k_scatter
__device__ int    g_rowptr[N_NODES + 1];
__device__ int    g_pos[N_NODES];
__device__ int    g_srcs[N_EDGES];
__device__ float2 g_ex[N_EDGES];                // staged x[src] per CSR edge slot
__device__ float  g_e2a[N_EDGES];               // staged a2s[src] per CSR edge slot
__device__ float4 g_e2h[N_EDGES];               // staged h2[src] per CSR edge slot
__device__ float4 g_h2[N_NODES];
__device__ float  g_a2s[N_NODES];
__device__ float  g_a2d[N_NODES];
__device__ float4 g_pq[8];                      // (ps,qs,pd,qd)*log2e per head

__device__ __forceinline__ float ex2f(float x) {
    float r;
    asm("ex2.approx.ftz.f32 %0, %1;" : "=f"(r) : "f"(x));
    return r;
}

// Per-warp int64-vs-int32 detection: for int64 edge data (values < 2^31),
// odd 32-bit words of the first 64 elements are all zero.
__device__ __forceinline__ int detect_is64(const int* __restrict__ ei) {
    int lane = threadIdx.x & 31;
    int nz = ei[2 * lane + 1] | ei[2 * (lane + 32) + 1];
#pragma unroll
    for (int off = 16; off > 0; off >>= 1) nz |= __shfl_xor_sync(0xffffffffu, nz, off);
    return nz == 0;
}

// ---------------- hist: 4 edges/thread, vector loads ----------------
__global__ void __launch_bounds__(256) k_hist(const int* __restrict__ ei) {
    int is64 = detect_is64(ei);
    int e0 = (blockIdx.x * blockDim.x + threadIdx.x) * 4;
    if (e0 >= N_EDGES) return;
    int d0, d1, d2, d3;
    if (is64) {
        const longlong2* p = (const longlong2*)((const long long*)ei + N_EDGES + e0);
        longlong2 a = __ldg(&p[0]);
        longlong2 b = __ldg(&p[1]);
        d0 = (int)a.x; d1 = (int)a.y; d2 = (int)b.x; d3 = (int)b.y;
    } else {
        int4 a = __ldg((const int4*)(ei + N_EDGES + e0));
        d0 = a.x; d1 = a.y; d2 = a.z; d3 = a.w;
    }
    if ((unsigned)d0 < (unsigned)N_NODES) atomicAdd(&g_deg[d0], 1);
    if ((unsigned)d1 < (unsigned)N_NODES) atomicAdd(&g_deg[d1], 1);
    if ((unsigned)d2 < (unsigned)N_NODES) atomicAdd(&g_deg[d2], 1);
    if ((unsigned)d3 < (unsigned)N_NODES) atomicAdd(&g_deg[d3], 1);
}

// ---------------- single-pass decoupled-lookback scan ----------------
__global__ void __launch_bounds__(SCAN_B) k_scan(const float* __restrict__ W1,
                                                 const float* __restrict__ as1,
                                                 const float* __restrict__ ad1) {
    __shared__ int wsum[32];
    __shared__ int s_base;
    int t = threadIdx.x;
    int b = blockIdx.x;
    int lane = t & 31;
    int wid = t >> 5;
    int i = b * SCAN_B + t;

    int v = 0;
    if (i < N_NODES) {
        v = g_deg[i];
        g_deg[i] = 0;  // restore invariant for next replay
    }
    int wi = v;
#pragma unroll
    for (int off = 1; off < 32; off <<= 1) {
        int u = __shfl_up_sync(0xffffffffu, wi, off);
        if (lane >= off) wi += u;
    }
    if (lane == 31) wsum[wid] = wi;
    __syncthreads();
    if (wid == 0) {
        int w = wsum[lane];
#pragma unroll
        for (int off = 1; off < 32; off <<= 1) {
            int u = __shfl_up_sync(0xffffffffu, w, off);
            if (lane >= off) w += u;
        }
        wsum[lane] = w;
    }
    __syncthreads();
    int incl = wi + (wid ? wsum[wid - 1] : 0);
    int blockTotal = wsum[31];

    if (t == 0) {
        if (b == 0) {
            atomicExch(&g_desc[0], (2ull << 32) | (unsigned)blockTotal);
            s_base = 0;
        } else {
            atomicExch(&g_desc[b], (1ull << 32) | (unsigned)blockTotal);
            long long sum = 0;
            int j = b - 1;
            for (;;) {
                unsigned long long d;
                do {
                    d = *(volatile unsigned long long*)&g_desc[j];
                } while ((d >> 32) == 0ull);
                sum += (int)(unsigned)(d & 0xffffffffull);
                if ((d >> 32) == 2ull) break;
                j--;
            }
            s_base = (int)sum;
            atomicExch(&g_desc[b], (2ull << 32) | (unsigned)(sum + blockTotal));
        }
    }
    __syncthreads();
    int base = s_base;
    if (i < N_NODES) {
        int exc = base + incl - v;
        g_rowptr[i] = exc;
        g_pos[i] = exc;
        if (i == N_NODES - 1) g_rowptr[N_NODES] = base + incl;
    }

    // rank-2 projection precompute (block 0, 8 threads)
    if (b == 0 && t < 8) {
        int h = t;
        float ps = 0.f, qs = 0.f, pd = 0.f, qd = 0.f;
        for (int c = 0; c < 16; c++) {
            int idx = h * 16 + c;
            float w0 = W1[idx], w1 = W1[128 + idx];
            float a = as1[idx], d = ad1[idx];
            ps += w0 * a;
            qs += w1 * a;
            pd += w0 * d;
            qd += w1 * d;
        }
        g_pq[h] = make_float4(ps * LOG2E, qs * LOG2E, pd * LOG2E, qd * LOG2E);
    }
}

// ---------------- scatter: 4 edges/thread; also stage x[src] per edge slot ----------------
__global__ void __launch_bounds__(256) k_scatter(const int* __restrict__ ei,
                                                 const float* __restrict__ x) {
    int is64 = detect_is64(ei);
    int gtid = blockIdx.x * blockDim.x + threadIdx.x;
    if (gtid < SCAN_NB) g_desc[gtid] = 0ull;  // restore for next replay
    int e0 = gtid * 4;
    if (e0 >= N_EDGES) return;
    const float2* x2 = (const float2*)x;
    int s0, s1, s2, s3, d0, d1, d2, d3;
    if (is64) {
        const longlong2* ps = (const longlong2*)((const long long*)ei + e0);
        const longlong2* pd = (const longlong2*)((const long long*)ei + N_EDGES + e0);
        longlong2 a = __ldg(&ps[0]), b = __ldg(&ps[1]);
        longlong2 c = __ldg(&pd[0]), d = __ldg(&pd[1]);
        s0 = (int)a.x; s1 = (int)a.y; s2 = (int)b.x; s3 = (int)b.y;
        d0 = (int)c.x; d1 = (int)c.y; d2 = (int)d.x; d3 = (int)d.y;
    } else {
        int4 a = __ldg((const int4*)(ei + e0));
        int4 c = __ldg((const int4*)(ei + N_EDGES + e0));
        s0 = a.x; s1 = a.y; s2 = a.z; s3 = a.w;
        d0 = c.x; d1 = c.y; d2 = c.z; d3 = c.w;
    }
#define SCAT(ss, dd)                                                            \
    if ((unsigned)(dd) < (unsigned)N_NODES && (unsigned)(ss) < (unsigned)N_NODES) { \
        int p = atomicAdd(&g_pos[dd], 1);                                       \
        if ((unsigned)p < (unsigned)N_EDGES) {                                  \
            g_srcs[p] = (ss);                                                   \
            g_ex[p] = __ldg(&x2[ss]);                                           \
        }                                                                       \
    }
    SCAT(s0, d0)
    SCAT(s1, d1)
    SCAT(s2, d2)
    SCAT(s3, d3)
#undef SCAT
}

// ---------------- layer 1: coalesced edge stream + node transform + W2 fold ----------------
// warp per dst node; lane = 8*edge_stripe + head (4 stripes x 8 heads)
__global__ void __launch_bounds__(256) k_layer1(
    const float* __restrict__ x,
    const float* __restrict__ W1,
    const float* __restrict__ b1,
    const float* __restrict__ W2,
    const float* __restrict__ as2,
    const float* __restrict__ ad2) {
    int warp = (blockIdx.x * blockDim.x + threadIdx.x) >> 5;
    if (warp >= N_NODES) return;
    int lane = threadIdx.x & 31;
    int h = lane & 7;
    int es = lane >> 3;

    float4 pq = g_pq[h];
    const float2* x2 = (const float2*)x;
    float2 xn = __ldg(&x2[warp]);
    float P = pq.x, Q = pq.y;
    float A = fmaf(xn.x, pq.z, xn.y * pq.w);  // log2e * a_dst[n,h]

    int beg = g_rowptr[warp];
    int end = g_rowptr[warp + 1];

    float S0 = 0.f, S1 = 0.f, SS = 0.f;
    for (int i = beg + es; i < end; i += 4) {
        float2 xs = g_ex[i];                        // coalesced/broadcast stream
        float t = fmaf(xs.y, Q, fmaf(xs.x, P, A));  // log2e*(a_src+a_dst)
        t = fmaxf(t, 0.2f * t);                     // leaky relu
        float ex = ex2f(t);                         // exp(lrelu(e))
        S0 = fmaf(ex, xs.x, S0);
        S1 = fmaf(ex, xs.y, S1);
        SS += ex;
    }
    // reduce over the 4 edge stripes
    S0 += __shfl_xor_sync(0xffffffffu, S0, 8);
    S0 += __shfl_xor_sync(0xffffffffu, S0, 16);
    S1 += __shfl_xor_sync(0xffffffffu, S1, 8);
    S1 += __shfl_xor_sync(0xffffffffu, S1, 16);
    SS += __shfl_xor_sync(0xffffffffu, SS, 8);
    SS += __shfl_xor_sync(0xffffffffu, SS, 16);

    // redistribute: lane l produces channels 4l..4l+3, head = l>>2
    int hl = lane >> 2;
    float s0 = __shfl_sync(0xffffffffu, S0, hl);
    float s1 = __shfl_sync(0xffffffffu, S1, hl);
    float ss = __shfl_sync(0xffffffffu, SS, hl);
    float inv = 1.0f / (ss + 1e-16f);

    // out1[c] = (S0*W1[0,c] + S1*W1[1,c])/sum + b1[c], relu; fold into W2
    float4 w1a = __ldg((const float4*)(W1 + 4 * lane));
    float4 w1b = __ldg((const float4*)(W1 + 128 + 4 * lane));
    float4 bb = __ldg((const float4*)(b1 + 4 * lane));
    float o0 = fmaxf(fmaf(s0, w1a.x, s1 * w1b.x) * inv + bb.x, 0.f);
    float o1 = fmaxf(fmaf(s0, w1a.y, s1 * w1b.y) * inv + bb.y, 0.f);
    float o2 = fmaxf(fmaf(s0, w1a.z, s1 * w1b.z) * inv + bb.z, 0.f);
    float o3 = fmaxf(fmaf(s0, w1a.w, s1 * w1b.w) * inv + bb.w, 0.f);
    float4 w20 = __ldg((const float4*)(W2 + (4 * lane + 0) * 4));
    float4 w21 = __ldg((const float4*)(W2 + (4 * lane + 1) * 4));
    float4 w22 = __ldg((const float4*)(W2 + (4 * lane + 2) * 4));
    float4 w23 = __ldg((const float4*)(W2 + (4 * lane + 3) * 4));
    float hp0 = o0 * w20.x + o1 * w21.x + o2 * w22.x + o3 * w23.x;
    float hp1 = o0 * w20.y + o1 * w21.y + o2 * w22.y + o3 * w23.y;
    float hp2 = o0 * w20.z + o1 * w21.z + o2 * w22.z + o3 * w23.z;
    float hp3 = o0 * w20.w + o1 * w21.w + o2 * w22.w + o3 * w23.w;
#pragma unroll
    for (int off = 16; off > 0; off >>= 1) {
        hp0 += __shfl_xor_sync(0xffffffffu, hp0, off);
        hp1 += __shfl_xor_sync(0xffffffffu, hp1, off);
        hp2 += __shfl_xor_sync(0xffffffffu, hp2, off);
        hp3 += __shfl_xor_sync(0xffffffffu, hp3, off);
    }
    if (lane == 0) {
        g_h2[warp] = make_float4(hp0, hp1, hp2, hp3);
        float4 a = __ldg((const float4*)as2);
        float4 d = __ldg((const float4*)ad2);
        g_a2s[warp] = (hp0 * a.x + hp1 * a.y + hp2 * a.z + hp3 * a.w) * LOG2E;
        g_a2d[warp] = (hp0 * d.x + hp1 * d.y + hp2 * d.z + hp3 * d.w) * LOG2E;
    }
}

// ---------------- stage2: gather (a2s, h2) of each edge's src into CSR order ----------------
__global__ void __launch_bounds__(256) k_stage2() {
    int e0 = (blockIdx.x * blockDim.x + threadIdx.x) * 4;
    if (e0 >= N_EDGES) return;
    int4 s4 = *(const int4*)(g_srcs + e0);
    float a0 = g_a2s[s4.x];
    float a1 = g_a2s[s4.y];
    float a2 = g_a2s[s4.z];
    float a3 = g_a2s[s4.w];
    float4 h0 = g_h2[s4.x];
    float4 h1 = g_h2[s4.y];
    float4 h2v = g_h2[s4.z];
    float4 h3 = g_h2[s4.w];
    *(float4*)(g_e2a + e0) = make_float4(a0, a1, a2, a3);
    g_e2h[e0 + 0] = h0;
    g_e2h[e0 + 1] = h1;
    g_e2h[e0 + 2] = h2v;
    g_e2h[e0 + 3] = h3;
}

// ---------------- layer 2: coalesced edge stream + bias + log_softmax ----------------
__global__ void __launch_bounds__(256) k_layer2(const float* __restrict__ b2,
                                                float* __restrict__ out) {
    int warp = (blockIdx.x * blockDim.x + threadIdx.x) >> 5;
    if (warp >= N_NODES) return;
    int lane = threadIdx.x & 31;

    float a2dn = g_a2d[warp];
    int beg = g_rowptr[warp];
    int end = g_rowptr[warp + 1];

    float a0 = 0.f, a1 = 0.f, a2 = 0.f, a3 = 0.f, ss = 0.f;
    for (int i = beg + lane; i < end; i += 32) {
        float t = g_e2a[i] + a2dn;
        t = fmaxf(t, 0.2f * t);
        float ex = ex2f(t);
        float4 hv = g_e2h[i];
        a0 = fmaf(ex, hv.x, a0);
        a1 = fmaf(ex, hv.y, a1);
        a2 = fmaf(ex, hv.z, a2);
        a3 = fmaf(ex, hv.w, a3);
        ss += ex;
    }
#pragma unroll
    for (int off = 16; off > 0; off >>= 1) {
        a0 += __shfl_xor_sync(0xffffffffu, a0, off);
        a1 += __shfl_xor_sync(0xffffffffu, a1, off);
        a2 += __shfl_xor_sync(0xffffffffu, a2, off);
        a3 += __shfl_xor_sync(0xffffffffu, a3, off);
        ss += __shfl_xor_sync(0xffffffffu, ss, off);
    }
    if (lane == 0) {
        float inv = 1.0f / (ss + 1e-16f);
        float4 bv = __ldg((const float4*)b2);
        float o0 = a0 * inv + bv.x;
        float o1 = a1 * inv + bv.y;
        float o2 = a2 * inv + bv.z;
        float o3 = a3 * inv + bv.w;
        float m = fmaxf(fmaxf(o0, o1), fmaxf(o2, o3));
        float se = expf(o0 - m) + expf(o1 - m) + expf(o2 - m) + expf(o3 - m);
        float ls = m + logf(se);
        ((float4*)out)[warp] = make_float4(o0 - ls, o1 - ls, o2 - ls, o3 - ls);
    }
}

// ---------------- launch ----------------
extern "C" void kernel_launch(void* const* d_in, const int* in_sizes, int n_in,
                              void* d_out, int out_size) {
    const float* x   = (const float*)d_in[0];
    const int*   ei  = (const int*)d_in[1];  // raw 32-bit view; dtype detected per-warp
    const float* W1  = (const float*)d_in[2];
    const float* as1 = (const float*)d_in[3];
    const float* ad1 = (const float*)d_in[4];
    const float* b1  = (const float*)d_in[5];
    const float* W2  = (const float*)d_in[6];
    const float* as2 = (const float*)d_in[7];
    const float* ad2 = (const float*)d_in[8];
    const float* b2  = (const float*)d_in[9];
    float*       out = (float*)d_out;

    int eb = (N_EDGES / 4 + 255) / 256;
    k_hist<<<eb, 256>>>(ei);
    k_scan<<<SCAN_NB, SCAN_B>>>(W1, as1, ad1);
    k_scatter<<<eb, 256>>>(ei, x);
    k_layer1<<<(N_NODES * 32 + 255) / 256, 256>>>(x, W1, b1, W2, as2, ad2);
    k_stage2<<<eb, 256>>>();
    k_layer2<<<(N_NODES * 32 + 255) / 256, 256>>>(b2, out);
}